// round 1
// baseline (speedup 1.0000x reference)
#include <cuda_runtime.h>
#include <math.h>

// Fixed problem geometry (from setup_inputs): D=128, H=8, PAGE_SIZE=16.
#define DD      128
#define HH      8
#define PAGE    16
#define BUDGET  4096
#define SINK    4
#define VEC_PER_ROW (DD/4)          // 32 float4 per head-row
#define VEC_PER_POS (HH*DD/4)       // 256 float4 per (b,pos) row

// inv_freq[i] = 10000^(-i/64), computed once in double for accuracy.
__device__ float g_invfreq[DD/2];

__global__ void init_invfreq_kernel() {
    int i = threadIdx.x;
    if (i < DD/2) g_invfreq[i] = (float)pow(10000.0, -(double)i / (double)(DD/2));
}

__global__ __launch_bounds__(256)
void skv_kernel(const float4* __restrict__ cache,   // (pages, 2, 16, H, D) fp32
                const float4* __restrict__ knew,    // (bsz, seq_len, H, D)
                const float4* __restrict__ vnew,    // (bsz, seq_len, H, D)
                const int*    __restrict__ qlens,   // (bsz,)
                const int*    __restrict__ ctxp,    // scalar context_len
                float4*       __restrict__ out,     // same layout as cache
                int maxkv, int seq_len, int nvec)
{
    int t = blockIdx.x * 256 + threadIdx.x;
    if (t >= nvec) return;

    // Decompose flat vec4 index: (page, kv, in_page, h, d4)
    int d4   = t & 31;              // float4 index along D
    int h    = (t >> 5) & (HH - 1);
    int ip   = (t >> 8) & (PAGE - 1);
    int kv   = (t >> 12) & 1;
    int page = t >> 13;

    int g = page * PAGE + ip;       // global position across batches
    int b = g / maxkv;
    int p = g - b * maxkv;

    int ctx = *ctxp;                // uniform, L2-cached
    int ql  = __ldg(&qlens[b]);
    bool active  = (ql > 0);
    bool rolling = active && (ctx + ql >  BUDGET);
    bool plain   = active && (ctx + ql <= BUDGET);

    // ---- resolve source row pointer (uniform per warp) ----
    const float4* row;
    if (rolling && p >= SINK && p < BUDGET - ql) {
        // shifted read from the cache itself
        int srs = min(ctx, BUDGET) - (BUDGET - ql - SINK);
        int pos = p + srs - SINK;
        pos = min(max(pos, 0), maxkv - 1);
        int gp = b * maxkv + pos;
        row = cache + (size_t)(((gp >> 4) * 2 + kv) * PAGE + (gp & 15)) * VEC_PER_POS
                    + h * VEC_PER_ROW;
    } else if ((rolling && p >= BUDGET - ql && p < BUDGET) ||
               (plain   && p >= ctx         && p < ctx + ql)) {
        // appended new tokens from k/v
        int sp = rolling ? (p - (BUDGET - ql)) : (p - ctx);
        sp = min(max(sp, 0), seq_len - 1);
        const float4* base = kv ? vnew : knew;
        row = base + ((size_t)(b * seq_len + sp) * HH + h) * VEC_PER_ROW;
    } else {
        // plain copy from cache
        int gp = b * maxkv + p;
        row = cache + (size_t)(((gp >> 4) * 2 + kv) * PAGE + (gp & 15)) * VEC_PER_POS
                    + h * VEC_PER_ROW;
    }

    if (kv == 0 && p < BUDGET) {
        // ---- RoPE on keys, positions [0, BUDGET) ----
        // out[d]      = x[d]*cos(ang_d)    - x[d+64]*sin(ang_d)     (d <  64)
        // out[64+i]   = x[i]*sin(ang_i)    + x[64+i]*cos(ang_i)     (i = d-64)
        int dd = d4 * 4;
        int i0 = (dd < 64) ? dd : (dd - 64);
        float4 x1 = row[i0 >> 2];          // floats [i0 .. i0+3]
        float4 x2 = row[(i0 >> 2) + 16];   // floats [i0+64 .. i0+67]
        // Partner loads fully overlap within the warp -> no extra DRAM traffic.
        float fp = (float)p;
        float4 o;
        const float* x1f = (const float*)&x1;
        const float* x2f = (const float*)&x2;
        float* of = (float*)&o;
        bool lower = (dd < 64);
        #pragma unroll
        for (int j = 0; j < 4; j++) {
            float s, c;
            sincosf(fp * g_invfreq[i0 + j], &s, &c);
            of[j] = lower ? (x1f[j] * c - x2f[j] * s)
                          : (x1f[j] * s + x2f[j] * c);
        }
        out[t] = o;
    } else {
        // values, and keys at p >= BUDGET: straight copy
        out[t] = __ldg(&row[d4]);
    }
}

extern "C" void kernel_launch(void* const* d_in, const int* in_sizes, int n_in,
                              void* d_out, int out_size) {
    const float4* cache = (const float4*)d_in[0];
    const float4* knew  = (const float4*)d_in[1];
    const float4* vnew  = (const float4*)d_in[2];
    const int*    qlens = (const int*)d_in[3];
    const int*    ctxp  = (const int*)d_in[5];   // context_len scalar (device)

    int bsz = in_sizes[3];                                  // len(query_lens)
    int total_pos = in_sizes[0] / (2 * HH * DD);            // positions across batches
    int maxkv = total_pos / bsz;                            // 8192
    int seq_len = in_sizes[1] / (bsz * HH * DD);            // 2048

    int nvec = out_size / 4;                                // float4 count
    int blocks = (nvec + 255) / 256;

    init_invfreq_kernel<<<1, 64>>>();
    skv_kernel<<<blocks, 256>>>(cache, knew, vnew, qlens, ctxp,
                                (float4*)d_out, maxkv, seq_len, nvec);
}